// round 6
// baseline (speedup 1.0000x reference)
#include <cuda_runtime.h>
#include <math.h>

#define BB 64
#define CC 2048
#define QQ 128
#define DD 128
#define CT 64
#define NSPLIT 16
#define MASKV (-1e30f)

// ----------------------------------------------------------------------------
// Device scratch (static globals: no allocation in kernel_launch)
// ----------------------------------------------------------------------------
__device__ float g_score[(size_t)BB * CC * QQ];   // 64 MB raw trilinear scores
__device__ float g_rc[BB * CC];                   // vfeats @ w4C
__device__ float g_cq[BB * QQ];                   // qfeats @ w4Q
__device__ float g_pm[BB * NSPLIT * QQ];          // partial col max
__device__ float g_ps[BB * NSPLIT * QQ];          // partial col expsum
__device__ float g_colmax[BB * QQ];
__device__ float g_colinv[BB * QQ];               // 1 / colsum
__device__ float g_mid[BB * QQ * DD];             // einsum('bcq,bcd->bqd', score_t, v)
__device__ float g_pproj[BB * DD];                // pooled @ cc_W[:,D:].T + cc_b
__device__ float g_qfT[BB * DD * QQ];             // qfeats transposed per batch [d][q]
__device__ float g_cqaWT[4 * DD * DD];            // cqa_W k-major: [part][k][d]
__device__ float g_ccWT[DD * DD];                 // cc_W[:, :D] k-major: [k][d]

// ----------------------------------------------------------------------------
// GEMM micro-kernels: 4x8 per-thread tile, K=128, all operands stride-128 fp32
// A read as rows (k fastest), B read k-major rows -> conflict-free LDS.128.
// ----------------------------------------------------------------------------
__device__ __forceinline__ void gemm_tile(const float* __restrict__ A,
                                          const float* __restrict__ Bm,
                                          float acc[4][8], int r0, int x0) {
#pragma unroll 2
    for (int k = 0; k < 128; k += 4) {
        float a[4][4];
#pragma unroll
        for (int i = 0; i < 4; i++) {
            float4 t = *(const float4*)(A + (r0 + i) * 128 + k);
            a[i][0] = t.x; a[i][1] = t.y; a[i][2] = t.z; a[i][3] = t.w;
        }
#pragma unroll
        for (int kk = 0; kk < 4; kk++) {
            float4 b0 = *(const float4*)(Bm + (k + kk) * 128 + x0);
            float4 b1 = *(const float4*)(Bm + (k + kk) * 128 + x0 + 4);
            float br[8] = {b0.x, b0.y, b0.z, b0.w, b1.x, b1.y, b1.z, b1.w};
#pragma unroll
            for (int i = 0; i < 4; i++)
#pragma unroll
                for (int j = 0; j < 8; j++)
                    acc[i][j] += a[i][kk] * br[j];
        }
    }
}

// A = elementwise product A1*A2 (for v*c2q and v*q2c parts of the cat GEMM)
__device__ __forceinline__ void gemm_tile2(const float* __restrict__ A1,
                                           const float* __restrict__ A2,
                                           const float* __restrict__ Bm,
                                           float acc[4][8], int r0, int x0) {
#pragma unroll 2
    for (int k = 0; k < 128; k += 4) {
        float a[4][4];
#pragma unroll
        for (int i = 0; i < 4; i++) {
            float4 t1 = *(const float4*)(A1 + (r0 + i) * 128 + k);
            float4 t2 = *(const float4*)(A2 + (r0 + i) * 128 + k);
            a[i][0] = t1.x * t2.x; a[i][1] = t1.y * t2.y;
            a[i][2] = t1.z * t2.z; a[i][3] = t1.w * t2.w;
        }
#pragma unroll
        for (int kk = 0; kk < 4; kk++) {
            float4 b0 = *(const float4*)(Bm + (k + kk) * 128 + x0);
            float4 b1 = *(const float4*)(Bm + (k + kk) * 128 + x0 + 4);
            float br[8] = {b0.x, b0.y, b0.z, b0.w, b1.x, b1.y, b1.z, b1.w};
#pragma unroll
            for (int i = 0; i < 4; i++)
#pragma unroll
                for (int j = 0; j < 8; j++)
                    acc[i][j] += a[i][kk] * br[j];
        }
    }
}

// ----------------------------------------------------------------------------
// Prep kernels
// ----------------------------------------------------------------------------
__global__ void prep_w(const float* __restrict__ cqa_W, const float* __restrict__ cc_W) {
    int i = blockIdx.x * blockDim.x + threadIdx.x;
    if (i < 4 * DD * DD) {
        int p = i / (DD * DD);
        int r = i % (DD * DD);
        int k = r / DD, d = r % DD;
        g_cqaWT[i] = cqa_W[d * (4 * DD) + p * DD + k];
    }
    if (i < DD * DD) {
        int k = i / DD, d = i % DD;
        g_ccWT[i] = cc_W[d * (2 * DD) + k];
    }
}

__global__ void prep_qfT(const float* __restrict__ qf) {
    int i = blockIdx.x * blockDim.x + threadIdx.x;
    if (i >= BB * DD * QQ) return;
    int q = i % QQ;
    int t = i / QQ;
    int d = t % DD;
    int b = t / DD;
    g_qfT[i] = qf[((size_t)(b * QQ + q)) * DD + d];
}

__global__ void prep_rc_cq(const float* __restrict__ vf, const float* __restrict__ qf,
                           const float* __restrict__ w4C, const float* __restrict__ w4Q) {
    int i = blockIdx.x * blockDim.x + threadIdx.x;
    if (i < BB * CC) {
        const float* row = vf + (size_t)i * DD;
        float s = 0.f;
#pragma unroll 4
        for (int d = 0; d < DD; d++) s += row[d] * w4C[d];
        g_rc[i] = s;
    }
    if (i < BB * QQ) {
        const float* row = qf + (size_t)i * DD;
        float s = 0.f;
#pragma unroll 4
        for (int d = 0; d < DD; d++) s += row[d] * w4Q[d];
        g_cq[i] = s;
    }
}

__global__ void zero_mid() {
    int i = blockIdx.x * blockDim.x + threadIdx.x;
    if (i < BB * QQ * DD) g_mid[i] = 0.f;
}

// ----------------------------------------------------------------------------
// Pooled query projection: alpha-softmax pool of qfeats, projected by cc_W[:,D:]
// ----------------------------------------------------------------------------
__global__ void pooled_kernel(const float* __restrict__ qf, const float* __restrict__ qmask,
                              const float* __restrict__ wp, const float* __restrict__ cc_W,
                              const float* __restrict__ cc_b) {
    __shared__ float sred[QQ];
    __shared__ float s_al[QQ];
    __shared__ float s_pool[DD];
    int b = blockIdx.x, t = threadIdx.x;

    const float* row = qf + (size_t)(b * QQ + t) * DD;
    float x = 0.f;
#pragma unroll 4
    for (int d = 0; d < DD; d++) x += row[d] * wp[d];
    x += (1.f - qmask[b * QQ + t]) * MASKV;

    sred[t] = x; __syncthreads();
    for (int s = 64; s > 0; s >>= 1) {
        if (t < s) sred[t] = fmaxf(sred[t], sred[t + s]);
        __syncthreads();
    }
    float m = sred[0]; __syncthreads();
    float e = __expf(x - m);
    sred[t] = e; __syncthreads();
    for (int s = 64; s > 0; s >>= 1) {
        if (t < s) sred[t] += sred[t + s];
        __syncthreads();
    }
    float inv = 1.f / sred[0];
    s_al[t] = e * inv; __syncthreads();

    float p = 0.f;
#pragma unroll 4
    for (int q = 0; q < QQ; q++) p += s_al[q] * qf[(size_t)(b * QQ + q) * DD + t];
    s_pool[t] = p; __syncthreads();

    float o = cc_b[t];
#pragma unroll 4
    for (int k = 0; k < DD; k++) o += s_pool[k] * cc_W[t * (2 * DD) + DD + k];
    g_pproj[b * DD + t] = o;
}

// ----------------------------------------------------------------------------
// Score GEMM: score[b,c,q] = rc[c] + cq[q] + sum_d (v[c,d]*w4mlu[d]) * qf[q,d]
// ----------------------------------------------------------------------------
__global__ __launch_bounds__(256) void score_kernel(const float* __restrict__ vf,
                                                    const float* __restrict__ w4mlu) {
    extern __shared__ float sm[];
    float* sA = sm;                 // [CT][DD]
    float* sB = sm + CT * DD;       // [DD][QQ] (qfT)
    float* s_mlu = sB + DD * QQ;    // [DD]

    int b = blockIdx.y, c0 = blockIdx.x * CT, tid = threadIdx.x;
    if (tid < DD) s_mlu[tid] = w4mlu[tid];
    __syncthreads();

    {
        const float* src = vf + (size_t)(b * CC + c0) * DD;
        for (int i = tid; i < CT * DD; i += 256) sA[i] = src[i] * s_mlu[i & (DD - 1)];
        const float4* qs = (const float4*)(g_qfT + (size_t)b * DD * QQ);
        float4* qd = (float4*)sB;
        for (int i = tid; i < DD * QQ / 4; i += 256) qd[i] = qs[i];
    }
    __syncthreads();

    int ty = tid >> 4, tx = tid & 15;
    int r0 = ty * 4, q0 = tx * 8;
    float acc[4][8];
#pragma unroll
    for (int i = 0; i < 4; i++)
#pragma unroll
        for (int j = 0; j < 8; j++) acc[i][j] = 0.f;

    gemm_tile(sA, sB, acc, r0, q0);

    float rcv[4], cqv[8];
#pragma unroll
    for (int i = 0; i < 4; i++) rcv[i] = g_rc[b * CC + c0 + r0 + i];
#pragma unroll
    for (int j = 0; j < 8; j++) cqv[j] = g_cq[b * QQ + q0 + j];

#pragma unroll
    for (int i = 0; i < 4; i++) {
        float* dst = g_score + ((size_t)(b * CC + c0 + r0 + i)) * QQ + q0;
        float4 o0 = make_float4(acc[i][0] + rcv[i] + cqv[0], acc[i][1] + rcv[i] + cqv[1],
                                acc[i][2] + rcv[i] + cqv[2], acc[i][3] + rcv[i] + cqv[3]);
        float4 o1 = make_float4(acc[i][4] + rcv[i] + cqv[4], acc[i][5] + rcv[i] + cqv[5],
                                acc[i][6] + rcv[i] + cqv[6], acc[i][7] + rcv[i] + cqv[7]);
        *(float4*)dst = o0;
        *(float4*)(dst + 4) = o1;
    }
}

// ----------------------------------------------------------------------------
// Column softmax stats over c (for score_t), split-K then combine
// ----------------------------------------------------------------------------
__global__ void colstats_part(const float* __restrict__ vmask) {
    int b = blockIdx.x, sp = blockIdx.y, q = threadIdx.x;
    int cbeg = sp * (CC / NSPLIT);
    float m = -1e38f, s = 0.f;
    for (int c = cbeg; c < cbeg + CC / NSPLIT; c++) {
        float x = g_score[((size_t)(b * CC + c)) * QQ + q] + (1.f - vmask[b * CC + c]) * MASKV;
        float mn = fmaxf(m, x);
        s = s * __expf(m - mn) + __expf(x - mn);
        m = mn;
    }
    g_pm[(b * NSPLIT + sp) * QQ + q] = m;
    g_ps[(b * NSPLIT + sp) * QQ + q] = s;
}

__global__ void colstats_comb() {
    int b = blockIdx.x, q = threadIdx.x;
    float m = -1e38f;
#pragma unroll
    for (int sp = 0; sp < NSPLIT; sp++) m = fmaxf(m, g_pm[(b * NSPLIT + sp) * QQ + q]);
    float s = 0.f;
#pragma unroll
    for (int sp = 0; sp < NSPLIT; sp++)
        s += g_ps[(b * NSPLIT + sp) * QQ + q] * __expf(g_pm[(b * NSPLIT + sp) * QQ + q] - m);
    g_colmax[b * QQ + q] = m;
    g_colinv[b * QQ + q] = 1.f / s;
}

// ----------------------------------------------------------------------------
// mid[b,q,d] = sum_c score_t[b,c,q] * v[b,c,d]  (split-K over c + atomicAdd)
// ----------------------------------------------------------------------------
__global__ __launch_bounds__(256) void mid_kernel(const float* __restrict__ vf,
                                                  const float* __restrict__ vmask) {
    __shared__ float s_st[16 * QQ];
    __shared__ float s_v[16 * DD];
    __shared__ float s_cm[QQ];
    __shared__ float s_ci[QQ];
    int b = blockIdx.x, sp = blockIdx.y, tid = threadIdx.x;
    int cbase = sp * (CC / NSPLIT);
    if (tid < QQ) {
        s_cm[tid] = g_colmax[b * QQ + tid];
        s_ci[tid] = g_colinv[b * QQ + tid];
    }
    int ty = tid >> 4, tx = tid & 15;
    int q0 = ty * 8, d0 = tx * 8;
    float acc[8][8];
#pragma unroll
    for (int i = 0; i < 8; i++)
#pragma unroll
        for (int j = 0; j < 8; j++) acc[i][j] = 0.f;

    for (int cc0 = 0; cc0 < CC / NSPLIT; cc0 += 16) {
        __syncthreads();
        for (int i = tid; i < 16 * QQ; i += 256) {
            int kc = i >> 7, col = i & 127;
            int c = cbase + cc0 + kc;
            float x = g_score[((size_t)(b * CC + c)) * QQ + col] +
                      (1.f - vmask[b * CC + c]) * MASKV;
            s_st[i] = __expf(x - s_cm[col]) * s_ci[col];
            s_v[i] = vf[((size_t)(b * CC + c)) * DD + col];
        }
        __syncthreads();
#pragma unroll 4
        for (int k = 0; k < 16; k++) {
            float4 a0 = *(const float4*)&s_st[k * QQ + q0];
            float4 a1 = *(const float4*)&s_st[k * QQ + q0 + 4];
            float4 b0 = *(const float4*)&s_v[k * DD + d0];
            float4 b1 = *(const float4*)&s_v[k * DD + d0 + 4];
            float av[8] = {a0.x, a0.y, a0.z, a0.w, a1.x, a1.y, a1.z, a1.w};
            float bv[8] = {b0.x, b0.y, b0.z, b0.w, b1.x, b1.y, b1.z, b1.w};
#pragma unroll
            for (int i = 0; i < 8; i++)
#pragma unroll
                for (int j = 0; j < 8; j++) acc[i][j] += av[i] * bv[j];
        }
    }
#pragma unroll
    for (int i = 0; i < 8; i++)
#pragma unroll
        for (int j = 0; j < 8; j++)
            atomicAdd(&g_mid[(size_t)(b * QQ + q0 + i) * DD + d0 + j], acc[i][j]);
}

// ----------------------------------------------------------------------------
// Mega-fused: row softmax -> c2q -> q2c -> cat@cqa_W.T -> @cc_W[:, :D].T
//             + pooled projection + bias + ReLU
// ----------------------------------------------------------------------------
__global__ __launch_bounds__(256) void fused_kernel(const float* __restrict__ vf,
                                                    const float* __restrict__ qf,
                                                    const float* __restrict__ qmask,
                                                    const float* __restrict__ cqa_b,
                                                    float* __restrict__ out) {
    extern __shared__ float sm[];
    float* s_sc  = sm;                  // [64][128] score_ then feats
    float* s_X   = s_sc + CT * DD;      // [128][128] rotating B operand
    float* s_c2q = s_X + DD * DD;       // [64][128]
    float* s_q2c = s_c2q + CT * DD;     // [64][128]
    float* s_v   = s_q2c + CT * DD;     // [64][128]

    int b = blockIdx.y;
    int c0 = blockIdx.x * CT;
    int tid = threadIdx.x;
    int warp = tid >> 5, lane = tid & 31;

    // Step 1: row softmax of score over q (qmask applied), warp per 8 rows
    {
        float qm[4];
#pragma unroll
        for (int j = 0; j < 4; j++)
            qm[j] = (1.f - qmask[b * QQ + lane + 32 * j]) * MASKV;
#pragma unroll
        for (int rr = 0; rr < 8; rr++) {
            int r = warp * 8 + rr;
            const float* src = g_score + ((size_t)(b * CC + c0 + r)) * QQ;
            float v[4], e[4];
#pragma unroll
            for (int j = 0; j < 4; j++) v[j] = src[lane + 32 * j] + qm[j];
            float m = fmaxf(fmaxf(v[0], v[1]), fmaxf(v[2], v[3]));
#pragma unroll
            for (int off = 16; off > 0; off >>= 1)
                m = fmaxf(m, __shfl_xor_sync(0xffffffffu, m, off));
            float s = 0.f;
#pragma unroll
            for (int j = 0; j < 4; j++) { e[j] = __expf(v[j] - m); s += e[j]; }
#pragma unroll
            for (int off = 16; off > 0; off >>= 1)
                s += __shfl_xor_sync(0xffffffffu, s, off);
            float inv = 1.f / s;
#pragma unroll
            for (int j = 0; j < 4; j++) s_sc[r * QQ + lane + 32 * j] = e[j] * inv;
        }
    }
    // loads: v tile and qfeats
    {
        const float4* src = (const float4*)(vf + ((size_t)(b * CC + c0)) * DD);
        float4* dst = (float4*)s_v;
        for (int i = tid; i < CT * DD / 4; i += 256) dst[i] = src[i];
        const float4* qs = (const float4*)(qf + (size_t)b * QQ * DD);
        float4* qd = (float4*)s_X;
        for (int i = tid; i < QQ * DD / 4; i += 256) qd[i] = qs[i];
    }
    __syncthreads();

    int ty = tid >> 4, tx = tid & 15;
    int r0 = ty * 4, x0 = tx * 8;

    float acc[4][8];
    // GEMM1: c2q = score_ @ qfeats
#pragma unroll
    for (int i = 0; i < 4; i++)
#pragma unroll
        for (int j = 0; j < 8; j++) acc[i][j] = 0.f;
    gemm_tile(s_sc, s_X, acc, r0, x0);
#pragma unroll
    for (int i = 0; i < 4; i++) {
        *(float4*)&s_c2q[(r0 + i) * DD + x0] =
            make_float4(acc[i][0], acc[i][1], acc[i][2], acc[i][3]);
        *(float4*)&s_c2q[(r0 + i) * DD + x0 + 4] =
            make_float4(acc[i][4], acc[i][5], acc[i][6], acc[i][7]);
    }
    __syncthreads();
    // load mid, GEMM2: q2c = score_ @ mid
    {
        const float4* src = (const float4*)(g_mid + (size_t)b * QQ * DD);
        float4* dst = (float4*)s_X;
        for (int i = tid; i < QQ * DD / 4; i += 256) dst[i] = src[i];
    }
    __syncthreads();
#pragma unroll
    for (int i = 0; i < 4; i++)
#pragma unroll
        for (int j = 0; j < 8; j++) acc[i][j] = 0.f;
    gemm_tile(s_sc, s_X, acc, r0, x0);
#pragma unroll
    for (int i = 0; i < 4; i++) {
        *(float4*)&s_q2c[(r0 + i) * DD + x0] =
            make_float4(acc[i][0], acc[i][1], acc[i][2], acc[i][3]);
        *(float4*)&s_q2c[(r0 + i) * DD + x0 + 4] =
            make_float4(acc[i][4], acc[i][5], acc[i][6], acc[i][7]);
    }
    __syncthreads();

    // feats = [v, c2q, v*c2q, v*q2c] @ cqa_W.T + cqa_b
    float facc[4][8];
    {
        float bias[8];
#pragma unroll
        for (int j = 0; j < 8; j++) bias[j] = cqa_b[x0 + j];
#pragma unroll
        for (int i = 0; i < 4; i++)
#pragma unroll
            for (int j = 0; j < 8; j++) facc[i][j] = bias[j];
    }
#pragma unroll 1
    for (int part = 0; part < 4; part++) {
        const float4* src = (const float4*)(g_cqaWT + part * DD * DD);
        float4* dst = (float4*)s_X;
        for (int i = tid; i < DD * DD / 4; i += 256) dst[i] = src[i];
        __syncthreads();
        if (part == 0)      gemm_tile(s_v, s_X, facc, r0, x0);
        else if (part == 1) gemm_tile(s_c2q, s_X, facc, r0, x0);
        else if (part == 2) gemm_tile2(s_v, s_c2q, s_X, facc, r0, x0);
        else                gemm_tile2(s_v, s_q2c, s_X, facc, r0, x0);
        __syncthreads();
    }

    // write feats into s_sc (score_ no longer needed), load ccWT
#pragma unroll
    for (int i = 0; i < 4; i++) {
        *(float4*)&s_sc[(r0 + i) * DD + x0] =
            make_float4(facc[i][0], facc[i][1], facc[i][2], facc[i][3]);
        *(float4*)&s_sc[(r0 + i) * DD + x0 + 4] =
            make_float4(facc[i][4], facc[i][5], facc[i][6], facc[i][7]);
    }
    {
        const float4* src = (const float4*)g_ccWT;
        float4* dst = (float4*)s_X;
        for (int i = tid; i < DD * DD / 4; i += 256) dst[i] = src[i];
    }
    __syncthreads();

    // out = relu(feats @ cc_W[:, :D].T + pproj)
    float oacc[4][8];
    {
        float pp[8];
#pragma unroll
        for (int j = 0; j < 8; j++) pp[j] = g_pproj[b * DD + x0 + j];
#pragma unroll
        for (int i = 0; i < 4; i++)
#pragma unroll
            for (int j = 0; j < 8; j++) oacc[i][j] = pp[j];
    }
    gemm_tile(s_sc, s_X, oacc, r0, x0);

#pragma unroll
    for (int i = 0; i < 4; i++) {
        float* dst = out + ((size_t)(b * CC + c0 + r0 + i)) * DD + x0;
        float4 o0 = make_float4(fmaxf(oacc[i][0], 0.f), fmaxf(oacc[i][1], 0.f),
                                fmaxf(oacc[i][2], 0.f), fmaxf(oacc[i][3], 0.f));
        float4 o1 = make_float4(fmaxf(oacc[i][4], 0.f), fmaxf(oacc[i][5], 0.f),
                                fmaxf(oacc[i][6], 0.f), fmaxf(oacc[i][7], 0.f));
        *(float4*)dst = o0;
        *(float4*)(dst + 4) = o1;
    }
}

// ----------------------------------------------------------------------------
// Launch
// ----------------------------------------------------------------------------
extern "C" void kernel_launch(void* const* d_in, const int* in_sizes, int n_in,
                              void* d_out, int out_size) {
    const float* vfeats = (const float*)d_in[0];
    const float* qfeats = (const float*)d_in[1];
    const float* vmask  = (const float*)d_in[2];
    const float* qmask  = (const float*)d_in[3];
    const float* w4C    = (const float*)d_in[4];
    const float* w4Q    = (const float*)d_in[5];
    const float* w4mlu  = (const float*)d_in[6];
    const float* cqa_W  = (const float*)d_in[7];
    const float* cqa_b  = (const float*)d_in[8];
    const float* wp     = (const float*)d_in[9];
    const float* cc_W   = (const float*)d_in[10];
    const float* cc_b   = (const float*)d_in[11];
    float* out = (float*)d_out;

    const int SCORE_SMEM = (CT * DD + DD * QQ + DD) * (int)sizeof(float);   // ~98.8 KB
    const int FUSED_SMEM = (CT * DD * 4 + DD * DD) * (int)sizeof(float);    // 192 KB
    cudaFuncSetAttribute(score_kernel, cudaFuncAttributeMaxDynamicSharedMemorySize, SCORE_SMEM);
    cudaFuncSetAttribute(fused_kernel, cudaFuncAttributeMaxDynamicSharedMemorySize, FUSED_SMEM);

    prep_w<<<(4 * DD * DD + 255) / 256, 256>>>(cqa_W, cc_W);
    prep_qfT<<<(BB * DD * QQ + 255) / 256, 256>>>(qfeats);
    prep_rc_cq<<<(BB * CC + 255) / 256, 256>>>(vfeats, qfeats, w4C, w4Q);
    zero_mid<<<(BB * QQ * DD + 255) / 256, 256>>>();
    pooled_kernel<<<BB, QQ>>>(qfeats, qmask, wp, cc_W, cc_b);
    score_kernel<<<dim3(CC / CT, BB), 256, SCORE_SMEM>>>(vfeats, w4mlu);
    colstats_part<<<dim3(BB, NSPLIT), QQ>>>(vmask);
    colstats_comb<<<BB, QQ>>>();
    mid_kernel<<<dim3(BB, NSPLIT), 256>>>(vfeats, vmask);
    fused_kernel<<<dim3(CC / CT, BB), 256, FUSED_SMEM>>>(vfeats, qfeats, qmask, cqa_b, out);
}

// round 7
// speedup vs baseline: 1.3337x; 1.3337x over previous
#include <cuda_runtime.h>
#include <math.h>

#define BB 64
#define CC 2048
#define QQ 128
#define DD 128
#define CT 64
#define NSPLIT 16
#define MASKV (-1e30f)
#define SAP 132   // A-tile word stride (conflict-free fragment loads)
#define SBP 136   // B-tile word stride (conflict-free fragment loads)

// ----------------------------------------------------------------------------
// Device scratch
// ----------------------------------------------------------------------------
__device__ float g_score[(size_t)BB * CC * QQ];
__device__ float g_rc[BB * CC];
__device__ float g_cq[BB * QQ];
__device__ float g_pm[BB * NSPLIT * QQ];
__device__ float g_ps[BB * NSPLIT * QQ];
__device__ float g_colmax[BB * QQ];
__device__ float g_colinv[BB * QQ];
__device__ float g_mid[BB * QQ * DD];
__device__ float g_pproj[BB * DD];
__device__ float g_qfT[BB * DD * QQ];     // [b][d][q]
__device__ float g_cqaWT[4 * DD * DD];    // [part][k][d]
__device__ float g_ccWT[DD * DD];         // [k][d]

// ----------------------------------------------------------------------------
// TF32 MMA helpers (3xTF32 split for ~fp32 accuracy on tensor pipe)
// ----------------------------------------------------------------------------
__device__ __forceinline__ void mma_tf32(float c[4], const unsigned a[4], const unsigned b[2]) {
    asm volatile(
        "mma.sync.aligned.m16n8k8.row.col.f32.tf32.tf32.f32 "
        "{%0,%1,%2,%3}, {%4,%5,%6,%7}, {%8,%9}, {%0,%1,%2,%3};"
        : "+f"(c[0]), "+f"(c[1]), "+f"(c[2]), "+f"(c[3])
        : "r"(a[0]), "r"(a[1]), "r"(a[2]), "r"(a[3]), "r"(b[0]), "r"(b[1]));
}

__device__ __forceinline__ unsigned f2tf(float x) {
    unsigned r;
    asm("cvt.rna.tf32.f32 %0, %1;" : "=r"(r) : "f"(x));
    return r;
}

__device__ __forceinline__ void tf_split(float x, unsigned& h, unsigned& l) {
    h = f2tf(x);
    l = f2tf(x - __uint_as_float(h));
}

// Warp computes C[wr0:wr0+32][wc0:wc0+NT*8] += A(64|128 x K) @ B(K x 128).
// A row-major stride SA words (optionally elementwise product with A2),
// B [k][n] stride SB words. 3xTF32: Ah*Bh + Al*Bh + Ah*Bl.
template <int NT, bool PROD>
__device__ __forceinline__ void mma_stage(const float* __restrict__ A,
                                          const float* __restrict__ A2,
                                          const float* __restrict__ B,
                                          float acc[2][NT][4],
                                          int wr0, int wc0, int lane,
                                          int SA, int SB, int K) {
    const int gr = lane >> 2, tg = lane & 3;
#pragma unroll 2
    for (int k0 = 0; k0 < K; k0 += 8) {
        unsigned ah[2][4], al[2][4];
#pragma unroll
        for (int rb = 0; rb < 2; rb++) {
            const float* p0 = A + (wr0 + rb * 16 + gr) * SA + k0 + tg;
            const float* p1 = A + (wr0 + rb * 16 + 8 + gr) * SA + k0 + tg;
            float v0 = p0[0], v1 = p1[0], v2 = p0[4], v3 = p1[4];
            if (PROD) {
                const float* q0 = A2 + (wr0 + rb * 16 + gr) * SA + k0 + tg;
                const float* q1 = A2 + (wr0 + rb * 16 + 8 + gr) * SA + k0 + tg;
                v0 *= q0[0]; v1 *= q1[0]; v2 *= q0[4]; v3 *= q1[4];
            }
            tf_split(v0, ah[rb][0], al[rb][0]);
            tf_split(v1, ah[rb][1], al[rb][1]);
            tf_split(v2, ah[rb][2], al[rb][2]);
            tf_split(v3, ah[rb][3], al[rb][3]);
        }
#pragma unroll
        for (int nt = 0; nt < NT; nt++) {
            int n = wc0 + nt * 8 + gr;
            float b0 = B[(k0 + tg) * SB + n];
            float b1 = B[(k0 + 4 + tg) * SB + n];
            unsigned bh[2], bl[2];
            tf_split(b0, bh[0], bl[0]);
            tf_split(b1, bh[1], bl[1]);
#pragma unroll
            for (int rb = 0; rb < 2; rb++) {
                mma_tf32(acc[rb][nt], ah[rb], bh);
                mma_tf32(acc[rb][nt], al[rb], bh);
                mma_tf32(acc[rb][nt], ah[rb], bl);
            }
        }
    }
}

// ----------------------------------------------------------------------------
// Prep kernels
// ----------------------------------------------------------------------------
__global__ void prep_w(const float* __restrict__ cqa_W, const float* __restrict__ cc_W) {
    int i = blockIdx.x * blockDim.x + threadIdx.x;
    if (i < 4 * DD * DD) {
        int p = i / (DD * DD);
        int r = i % (DD * DD);
        int k = r / DD, d = r % DD;
        g_cqaWT[i] = cqa_W[d * (4 * DD) + p * DD + k];
    }
    if (i < DD * DD) {
        int k = i / DD, d = i % DD;
        g_ccWT[i] = cc_W[d * (2 * DD) + k];
    }
}

__global__ void prep_qfT(const float* __restrict__ qf) {
    int i = blockIdx.x * blockDim.x + threadIdx.x;
    if (i >= BB * DD * QQ) return;
    int q = i % QQ;
    int t = i / QQ;
    int d = t % DD;
    int b = t / DD;
    g_qfT[i] = qf[((size_t)(b * QQ + q)) * DD + d];
}

__global__ void prep_rc_cq(const float* __restrict__ vf, const float* __restrict__ qf,
                           const float* __restrict__ w4C, const float* __restrict__ w4Q) {
    int i = blockIdx.x * blockDim.x + threadIdx.x;
    if (i < BB * CC) {
        const float* row = vf + (size_t)i * DD;
        float s = 0.f;
#pragma unroll 4
        for (int d = 0; d < DD; d++) s += row[d] * w4C[d];
        g_rc[i] = s;
    }
    if (i < BB * QQ) {
        const float* row = qf + (size_t)i * DD;
        float s = 0.f;
#pragma unroll 4
        for (int d = 0; d < DD; d++) s += row[d] * w4Q[d];
        g_cq[i] = s;
    }
}

__global__ void zero_mid() {
    int i = blockIdx.x * blockDim.x + threadIdx.x;
    if (i < BB * QQ * DD) g_mid[i] = 0.f;
}

// ----------------------------------------------------------------------------
// Pooled query projection
// ----------------------------------------------------------------------------
__global__ void pooled_kernel(const float* __restrict__ qf, const float* __restrict__ qmask,
                              const float* __restrict__ wp, const float* __restrict__ cc_W,
                              const float* __restrict__ cc_b) {
    __shared__ float sred[QQ];
    __shared__ float s_al[QQ];
    __shared__ float s_pool[DD];
    int b = blockIdx.x, t = threadIdx.x;

    const float* row = qf + (size_t)(b * QQ + t) * DD;
    float x = 0.f;
#pragma unroll 4
    for (int d = 0; d < DD; d++) x += row[d] * wp[d];
    x += (1.f - qmask[b * QQ + t]) * MASKV;

    sred[t] = x; __syncthreads();
    for (int s = 64; s > 0; s >>= 1) {
        if (t < s) sred[t] = fmaxf(sred[t], sred[t + s]);
        __syncthreads();
    }
    float m = sred[0]; __syncthreads();
    float e = __expf(x - m);
    sred[t] = e; __syncthreads();
    for (int s = 64; s > 0; s >>= 1) {
        if (t < s) sred[t] += sred[t + s];
        __syncthreads();
    }
    float inv = 1.f / sred[0];
    s_al[t] = e * inv; __syncthreads();

    float p = 0.f;
#pragma unroll 4
    for (int q = 0; q < QQ; q++) p += s_al[q] * qf[(size_t)(b * QQ + q) * DD + t];
    s_pool[t] = p; __syncthreads();

    float o = cc_b[t];
#pragma unroll 4
    for (int k = 0; k < DD; k++) o += s_pool[k] * cc_W[t * (2 * DD) + DD + k];
    g_pproj[b * DD + t] = o;
}

// ----------------------------------------------------------------------------
// Score GEMM (MMA): score[c,q] = rc[c] + cq[q] + (v*mlu) @ qfT
// ----------------------------------------------------------------------------
__global__ __launch_bounds__(256) void score_kernel(const float* __restrict__ vf,
                                                    const float* __restrict__ w4mlu) {
    extern __shared__ float sm[];
    float* sA = sm;                   // [64][SAP]
    float* sB = sA + CT * SAP;        // [128][SBP]
    float* s_mlu = sB + DD * SBP;     // [128]

    int b = blockIdx.y, c0 = blockIdx.x * CT, tid = threadIdx.x;
    if (tid < DD) s_mlu[tid] = w4mlu[tid];
    __syncthreads();

    {
        const float* src = vf + (size_t)(b * CC + c0) * DD;
        for (int i = tid; i < CT * DD; i += 256) {
            int r = i >> 7, c = i & 127;
            sA[r * SAP + c] = src[i] * s_mlu[c];
        }
        const float* qs = g_qfT + (size_t)b * DD * QQ;
        for (int i = tid; i < DD * QQ; i += 256) {
            int d = i >> 7, q = i & 127;
            sB[d * SBP + q] = qs[i];
        }
    }
    __syncthreads();

    int warp = tid >> 5, lane = tid & 31;
    int gr = lane >> 2, tg = lane & 3;
    int wr0 = (warp & 1) * 32, wc0 = (warp >> 1) * 32;

    float acc[2][4][4];
#pragma unroll
    for (int rb = 0; rb < 2; rb++)
#pragma unroll
        for (int nt = 0; nt < 4; nt++)
#pragma unroll
            for (int j = 0; j < 4; j++) acc[rb][nt][j] = 0.f;

    mma_stage<4, false>(sA, nullptr, sB, acc, wr0, wc0, lane, SAP, SBP, 128);

#pragma unroll
    for (int rb = 0; rb < 2; rb++) {
        int r = wr0 + rb * 16 + gr;
        float rc0 = g_rc[b * CC + c0 + r];
        float rc1 = g_rc[b * CC + c0 + r + 8];
#pragma unroll
        for (int nt = 0; nt < 4; nt++) {
            int q = wc0 + nt * 8 + 2 * tg;
            float cq0 = g_cq[b * QQ + q], cq1 = g_cq[b * QQ + q + 1];
            float* d0 = g_score + ((size_t)(b * CC + c0 + r)) * QQ + q;
            float* d1 = g_score + ((size_t)(b * CC + c0 + r + 8)) * QQ + q;
            *(float2*)d0 = make_float2(acc[rb][nt][0] + rc0 + cq0, acc[rb][nt][1] + rc0 + cq1);
            *(float2*)d1 = make_float2(acc[rb][nt][2] + rc1 + cq0, acc[rb][nt][3] + rc1 + cq1);
        }
    }
}

// ----------------------------------------------------------------------------
// Column softmax stats (split over c)
// ----------------------------------------------------------------------------
__global__ void colstats_part(const float* __restrict__ vmask) {
    int b = blockIdx.x, sp = blockIdx.y, q = threadIdx.x;
    int cbeg = sp * (CC / NSPLIT);
    float m = -1e38f, s = 0.f;
    for (int c = cbeg; c < cbeg + CC / NSPLIT; c++) {
        float x = g_score[((size_t)(b * CC + c)) * QQ + q] + (1.f - vmask[b * CC + c]) * MASKV;
        float mn = fmaxf(m, x);
        s = s * __expf(m - mn) + __expf(x - mn);
        m = mn;
    }
    g_pm[(b * NSPLIT + sp) * QQ + q] = m;
    g_ps[(b * NSPLIT + sp) * QQ + q] = s;
}

__global__ void colstats_comb() {
    int b = blockIdx.x, q = threadIdx.x;
    float m = -1e38f;
#pragma unroll
    for (int sp = 0; sp < NSPLIT; sp++) m = fmaxf(m, g_pm[(b * NSPLIT + sp) * QQ + q]);
    float s = 0.f;
#pragma unroll
    for (int sp = 0; sp < NSPLIT; sp++)
        s += g_ps[(b * NSPLIT + sp) * QQ + q] * __expf(g_pm[(b * NSPLIT + sp) * QQ + q] - m);
    g_colmax[b * QQ + q] = m;
    g_colinv[b * QQ + q] = 1.f / s;
}

// ----------------------------------------------------------------------------
// mid[q,d] = sum_c score_t[c,q] * v[c,d]   (MMA split-K + atomicAdd)
// ----------------------------------------------------------------------------
#define STS 20   // s_stT word stride
__global__ __launch_bounds__(256) void mid_kernel(const float* __restrict__ vf,
                                                  const float* __restrict__ vmask) {
    __shared__ float s_stT[QQ * STS];   // [q][kc]
    __shared__ float s_v[16 * SBP];     // [kc][d]
    __shared__ float s_cm[QQ];
    __shared__ float s_ci[QQ];
    int b = blockIdx.x, sp = blockIdx.y, tid = threadIdx.x;
    int cbase = sp * (CC / NSPLIT);
    if (tid < QQ) {
        s_cm[tid] = g_colmax[b * QQ + tid];
        s_ci[tid] = g_colinv[b * QQ + tid];
    }
    int warp = tid >> 5, lane = tid & 31;
    int gr = lane >> 2, tg = lane & 3;
    int wr0 = (warp & 3) * 32, wc0 = (warp >> 2) * 64;

    float acc[2][8][4];
#pragma unroll
    for (int rb = 0; rb < 2; rb++)
#pragma unroll
        for (int nt = 0; nt < 8; nt++)
#pragma unroll
            for (int j = 0; j < 4; j++) acc[rb][nt][j] = 0.f;

    for (int cc0 = 0; cc0 < CC / NSPLIT; cc0 += 16) {
        __syncthreads();
        for (int i = tid; i < 16 * QQ; i += 256) {
            int kc = i >> 7, col = i & 127;
            int c = cbase + cc0 + kc;
            float x = g_score[((size_t)(b * CC + c)) * QQ + col] +
                      (1.f - vmask[b * CC + c]) * MASKV;
            s_stT[col * STS + kc] = __expf(x - s_cm[col]) * s_ci[col];
            s_v[kc * SBP + col] = vf[((size_t)(b * CC + c)) * DD + col];
        }
        __syncthreads();
        mma_stage<8, false>(s_stT, nullptr, s_v, acc, wr0, wc0, lane, STS, SBP, 16);
    }

#pragma unroll
    for (int rb = 0; rb < 2; rb++) {
        int q = wr0 + rb * 16 + gr;
#pragma unroll
        for (int nt = 0; nt < 8; nt++) {
            int d = wc0 + nt * 8 + 2 * tg;
            atomicAdd(&g_mid[(size_t)(b * QQ + q) * DD + d],     acc[rb][nt][0]);
            atomicAdd(&g_mid[(size_t)(b * QQ + q) * DD + d + 1], acc[rb][nt][1]);
            atomicAdd(&g_mid[(size_t)(b * QQ + q + 8) * DD + d],     acc[rb][nt][2]);
            atomicAdd(&g_mid[(size_t)(b * QQ + q + 8) * DD + d + 1], acc[rb][nt][3]);
        }
    }
}

// ----------------------------------------------------------------------------
// Mega-fused: row softmax -> c2q -> q2c -> cat@cqa_W.T -> @cc_W[:, :D].T
//             + pooled projection + ReLU (all GEMMs on tensor pipe)
// ----------------------------------------------------------------------------
__global__ __launch_bounds__(256, 1) void fused_kernel(const float* __restrict__ vf,
                                                       const float* __restrict__ qf,
                                                       const float* __restrict__ qmask,
                                                       const float* __restrict__ cqa_b,
                                                       float* __restrict__ out) {
    extern __shared__ float sm[];
    float* s_sc  = sm;                   // [64][SAP] score_ then feats
    float* s_v   = s_sc + CT * SAP;      // [64][SAP]
    float* s_c2q = s_v + CT * SAP;       // [64][SAP]
    float* s_q2c = s_c2q + CT * SAP;     // [64][SAP]
    float* s_B   = s_q2c + CT * SAP;     // [128][SBP] rotating B operand

    int b = blockIdx.y;
    int c0 = blockIdx.x * CT;
    int tid = threadIdx.x;
    int warp = tid >> 5, lane = tid & 31;
    int gr = lane >> 2, tg = lane & 3;
    int wr0 = (warp & 1) * 32, wc0 = (warp >> 1) * 32;

    // Step 1: row softmax of score over q
    {
        float qm[4];
#pragma unroll
        for (int j = 0; j < 4; j++)
            qm[j] = (1.f - qmask[b * QQ + lane + 32 * j]) * MASKV;
#pragma unroll
        for (int rr = 0; rr < 8; rr++) {
            int r = warp * 8 + rr;
            const float* src = g_score + ((size_t)(b * CC + c0 + r)) * QQ;
            float v[4], e[4];
#pragma unroll
            for (int j = 0; j < 4; j++) v[j] = src[lane + 32 * j] + qm[j];
            float m = fmaxf(fmaxf(v[0], v[1]), fmaxf(v[2], v[3]));
#pragma unroll
            for (int off = 16; off > 0; off >>= 1)
                m = fmaxf(m, __shfl_xor_sync(0xffffffffu, m, off));
            float s = 0.f;
#pragma unroll
            for (int j = 0; j < 4; j++) { e[j] = __expf(v[j] - m); s += e[j]; }
#pragma unroll
            for (int off = 16; off > 0; off >>= 1)
                s += __shfl_xor_sync(0xffffffffu, s, off);
            float inv = 1.f / s;
#pragma unroll
            for (int j = 0; j < 4; j++) s_sc[r * SAP + lane + 32 * j] = e[j] * inv;
        }
    }
    // load v tile (A-format) and qfeats (B-format)
    {
        const float* src = vf + ((size_t)(b * CC + c0)) * DD;
        for (int i = tid; i < CT * DD; i += 256)
            s_v[(i >> 7) * SAP + (i & 127)] = src[i];
        const float* qs = qf + (size_t)b * QQ * DD;
        for (int i = tid; i < QQ * DD; i += 256)
            s_B[(i >> 7) * SBP + (i & 127)] = qs[i];
    }
    __syncthreads();

    float acc[2][4][4];
#define ZERO_ACC(A_)                                      \
    _Pragma("unroll") for (int rb = 0; rb < 2; rb++)      \
    _Pragma("unroll") for (int nt = 0; nt < 4; nt++)      \
    _Pragma("unroll") for (int j = 0; j < 4; j++) A_[rb][nt][j] = 0.f;

#define STORE_ACC(DST, A_)                                                      \
    _Pragma("unroll") for (int rb = 0; rb < 2; rb++) {                          \
        int r_ = wr0 + rb * 16 + gr;                                            \
        _Pragma("unroll") for (int nt = 0; nt < 4; nt++) {                      \
            int cI = wc0 + nt * 8 + 2 * tg;                                     \
            (DST)[r_ * SAP + cI]       = A_[rb][nt][0];                         \
            (DST)[r_ * SAP + cI + 1]   = A_[rb][nt][1];                         \
            (DST)[(r_ + 8) * SAP + cI]     = A_[rb][nt][2];                     \
            (DST)[(r_ + 8) * SAP + cI + 1] = A_[rb][nt][3];                     \
        }                                                                       \
    }

    // GEMM1: c2q = score_ @ qfeats
    ZERO_ACC(acc)
    mma_stage<4, false>(s_sc, nullptr, s_B, acc, wr0, wc0, lane, SAP, SBP, 128);
    STORE_ACC(s_c2q, acc)
    __syncthreads();

    // GEMM2: q2c = score_ @ mid
    {
        const float* src = g_mid + (size_t)b * QQ * DD;
        for (int i = tid; i < QQ * DD; i += 256)
            s_B[(i >> 7) * SBP + (i & 127)] = src[i];
    }
    __syncthreads();
    ZERO_ACC(acc)
    mma_stage<4, false>(s_sc, nullptr, s_B, acc, wr0, wc0, lane, SAP, SBP, 128);
    STORE_ACC(s_q2c, acc)
    __syncthreads();

    // feats = [v, c2q, v*c2q, v*q2c] @ cqa_W.T + cqa_b
    float facc[2][4][4];
#pragma unroll
    for (int rb = 0; rb < 2; rb++)
#pragma unroll
        for (int nt = 0; nt < 4; nt++) {
            int d = wc0 + nt * 8 + 2 * tg;
            float b0 = cqa_b[d], b1 = cqa_b[d + 1];
            facc[rb][nt][0] = b0; facc[rb][nt][1] = b1;
            facc[rb][nt][2] = b0; facc[rb][nt][3] = b1;
        }
#pragma unroll 1
    for (int part = 0; part < 4; part++) {
        const float* src = g_cqaWT + part * DD * DD;
        for (int i = tid; i < DD * DD; i += 256)
            s_B[(i >> 7) * SBP + (i & 127)] = src[i];
        __syncthreads();
        if (part == 0)
            mma_stage<4, false>(s_v, nullptr, s_B, facc, wr0, wc0, lane, SAP, SBP, 128);
        else if (part == 1)
            mma_stage<4, false>(s_c2q, nullptr, s_B, facc, wr0, wc0, lane, SAP, SBP, 128);
        else if (part == 2)
            mma_stage<4, true>(s_v, s_c2q, s_B, facc, wr0, wc0, lane, SAP, SBP, 128);
        else
            mma_stage<4, true>(s_v, s_q2c, s_B, facc, wr0, wc0, lane, SAP, SBP, 128);
        __syncthreads();
    }

    // feats -> s_sc (score_ dead), load ccWT
    STORE_ACC(s_sc, facc)
    {
        for (int i = tid; i < DD * DD; i += 256)
            s_B[(i >> 7) * SBP + (i & 127)] = g_ccWT[i];
    }
    __syncthreads();

    // out = relu(feats @ cc_W[:, :D].T + pproj)
    float oacc[2][4][4];
#pragma unroll
    for (int rb = 0; rb < 2; rb++)
#pragma unroll
        for (int nt = 0; nt < 4; nt++) {
            int d = wc0 + nt * 8 + 2 * tg;
            float p0 = g_pproj[b * DD + d], p1 = g_pproj[b * DD + d + 1];
            oacc[rb][nt][0] = p0; oacc[rb][nt][1] = p1;
            oacc[rb][nt][2] = p0; oacc[rb][nt][3] = p1;
        }
    mma_stage<4, false>(s_sc, nullptr, s_B, oacc, wr0, wc0, lane, SAP, SBP, 128);

#pragma unroll
    for (int rb = 0; rb < 2; rb++) {
        int r = wr0 + rb * 16 + gr;
#pragma unroll
        for (int nt = 0; nt < 4; nt++) {
            int d = wc0 + nt * 8 + 2 * tg;
            float* d0 = out + ((size_t)(b * CC + c0 + r)) * DD + d;
            float* d1 = out + ((size_t)(b * CC + c0 + r + 8)) * DD + d;
            *(float2*)d0 = make_float2(fmaxf(oacc[rb][nt][0], 0.f), fmaxf(oacc[rb][nt][1], 0.f));
            *(float2*)d1 = make_float2(fmaxf(oacc[rb][nt][2], 0.f), fmaxf(oacc[rb][nt][3], 0.f));
        }
    }
}

// ----------------------------------------------------------------------------
// Launch
// ----------------------------------------------------------------------------
extern "C" void kernel_launch(void* const* d_in, const int* in_sizes, int n_in,
                              void* d_out, int out_size) {
    const float* vfeats = (const float*)d_in[0];
    const float* qfeats = (const float*)d_in[1];
    const float* vmask  = (const float*)d_in[2];
    const float* qmask  = (const float*)d_in[3];
    const float* w4C    = (const float*)d_in[4];
    const float* w4Q    = (const float*)d_in[5];
    const float* w4mlu  = (const float*)d_in[6];
    const float* cqa_W  = (const float*)d_in[7];
    const float* cqa_b  = (const float*)d_in[8];
    const float* wp     = (const float*)d_in[9];
    const float* cc_W   = (const float*)d_in[10];
    const float* cc_b   = (const float*)d_in[11];
    float* out = (float*)d_out;

    const int SCORE_SMEM = (CT * SAP + DD * SBP + DD) * (int)sizeof(float);
    const int FUSED_SMEM = (4 * CT * SAP + DD * SBP) * (int)sizeof(float);
    cudaFuncSetAttribute(score_kernel, cudaFuncAttributeMaxDynamicSharedMemorySize, SCORE_SMEM);
    cudaFuncSetAttribute(fused_kernel, cudaFuncAttributeMaxDynamicSharedMemorySize, FUSED_SMEM);

    prep_w<<<(4 * DD * DD + 255) / 256, 256>>>(cqa_W, cc_W);
    prep_qfT<<<(BB * DD * QQ + 255) / 256, 256>>>(qfeats);
    prep_rc_cq<<<(BB * CC + 255) / 256, 256>>>(vfeats, qfeats, w4C, w4Q);
    zero_mid<<<(BB * QQ * DD + 255) / 256, 256>>>();
    pooled_kernel<<<BB, QQ>>>(qfeats, qmask, wp, cc_W, cc_b);
    score_kernel<<<dim3(CC / CT, BB), 256, SCORE_SMEM>>>(vfeats, w4mlu);
    colstats_part<<<dim3(BB, NSPLIT), QQ>>>(vmask);
    colstats_comb<<<BB, QQ>>>();
    mid_kernel<<<dim3(BB, NSPLIT), 256>>>(vfeats, vmask);
    fused_kernel<<<dim3(CC / CT, BB), 256, FUSED_SMEM>>>(vfeats, qfeats, qmask, cqa_b, out);
}